// round 15
// baseline (speedup 1.0000x reference)
#include <cuda_runtime.h>

typedef unsigned long long ull;

#define BATCH 36
#define TWIN 60
#define DECAY 0.3f
#define THRESH 0.5f
#define NBLOCKS 296

// packed f32x2 fma: d = a*b + d per 32-bit lane (bit-exact IEEE fma per lane)
#define FMA2(d, a, b) asm("fma.rn.f32x2 %0, %1, %2, %0;" : "+l"(d) : "l"(a), "l"(b))

union F2 { ull u; float2 f; };

__device__ __forceinline__ ull dup2(float v) {
    F2 d; d.f.x = v; d.f.y = v; return d.u;
}

// ---------------- persistent LIAF state: pre = (m>THRESH) ? 0 : m*DECAY ----------
__device__ __align__(16) float g_c0_pre[BATCH*64*32*32];
__device__ __align__(16) float g_c1_pre[BATCH*128*32*32];
__device__ __align__(16) float g_p1_pre[BATCH*128*16*16];
__device__ __align__(16) float g_c2_pre[BATCH*128*16*16];
__device__ __align__(16) float g_p2_pre[BATCH*128*8*8];
__device__ __align__(16) float g_h1_pre[BATCH*256];
__device__ __align__(16) float g_h2_pre[BATCH*11];
__device__ __align__(16) float g_acc[BATCH*11];

// ---------------- parity double-buffered activations ----------------
__device__ __align__(16) float g_act0 [2][BATCH*64*32*32];
__device__ __align__(16) float g_actp1[2][BATCH*128*16*16];
__device__ __align__(16) float g_actp2[2][BATCH*128*8*8];
__device__ __align__(16) float g_acth1[2][BATCH*256];

// ---------------- pre-binarized input, t-major: [t][b*2+ic][y][x] ----------------
__device__ __align__(16) float g_bin[TWIN*BATCH*2*32*32];

// ---------------- transposed weights: Wt[c][oc], c = ic*9 + k ----------------
__device__ __align__(16) float g_Wt1[576*128];   // conv1: 64*9 x 128
__device__ __align__(16) float g_Wt2[1152*128];  // conv2: 128*9 x 128

// ---------------- global barrier state ----------------
__device__ unsigned g_bar_count;
__device__ unsigned g_bar_epoch;

__device__ __forceinline__ float liaf_pre(float u, float* prep) {
    float m = *prep + u;
    *prep = (m > THRESH) ? 0.0f : m * DECAY;
    return fmaxf(m, 0.0f);
}

// ---------------- zero state (+ barrier reset) ----------------
__global__ void zero_state_kernel() {
    int i = blockIdx.x * blockDim.x + threadIdx.x;
    if (i == 0) { g_bar_count = 0u; g_bar_epoch = 0u; }
    if (i < BATCH*64*32*32)  g_c0_pre[i] = 0.f;
    if (i < BATCH*128*32*32) g_c1_pre[i] = 0.f;
    if (i < BATCH*128*16*16) { g_p1_pre[i] = 0.f; g_c2_pre[i] = 0.f; }
    if (i < BATCH*128*8*8)   g_p2_pre[i] = 0.f;
    if (i < BATCH*256)       g_h1_pre[i] = 0.f;
    if (i < BATCH*11)        { g_h2_pre[i] = 0.f; g_acc[i] = 0.f; }
}

// ---------------- weight transpose (once per launch) ----------------
__global__ void prep_weights_kernel(const float* __restrict__ W1,
                                    const float* __restrict__ W2) {
    int i = blockIdx.x * blockDim.x + threadIdx.x;
    if (i < 576*128)  g_Wt1[i] = W1[(i & 127)*576  + (i >> 7)];
    if (i < 1152*128) g_Wt2[i] = W2[(i & 127)*1152 + (i >> 7)];
}

// ---------------- input binarize + transpose (once per launch) ----------------
__global__ void prep_bin_kernel(const float* __restrict__ data) {
    int i = blockIdx.x * blockDim.x + threadIdx.x;
    if (i >= TWIN*BATCH*2*32*32) return;
    int t = i / 73728, sp = i - t * 73728;
    g_bin[i] = (data[(size_t)sp * TWIN + t] > 1.0f) ? 1.0f : 0.0f;
}

// ---------------- device grid barrier (all NBLOCKS blocks) ----------------
__device__ __forceinline__ void grid_barrier(unsigned& epoch) {
    __syncthreads();
    if (threadIdx.x == 0) {
        __threadfence();                       // publish this block's writes
        unsigned arrived = atomicAdd(&g_bar_count, 1u);
        if (arrived == NBLOCKS - 1u) {
            g_bar_count = 0u;
            __threadfence();
            atomicAdd(&g_bar_epoch, 1u);       // release
        } else {
            unsigned target = epoch + 1u, e;
            do {
                asm volatile("ld.acquire.gpu.u32 %0, [%1];"
                             : "=r"(e) : "l"(&g_bar_epoch) : "memory");
                if (e < target) __nanosleep(64);
            } while (e < target);
        }
    }
    __syncthreads();
    epoch += 1u;
    __threadfence();   // gpu-scope fence: drop stale L1 lines before next phase
}

// ---------------- conv0 batch: stage weights once, run n tiles ----------------
__device__ __forceinline__ void conv0_batch(
    float* __restrict__ smem,
    const float* __restrict__ W0, const float* __restrict__ b0,
    float* __restrict__ act0_out, int t, int u0, int n)
{
    float* xs = smem;            // [2][10][12] = 240
    float* ws = smem + 240;      // [64][19]    = 1216
    int tid = threadIdx.x;
    const float* bt = g_bin + (size_t)t * 73728;

    __syncthreads();
    for (int i = tid; i < 1152; i += 256) {
        int oc = i / 18, r = i % 18;
        ws[oc*19 + r] = W0[i];
    }

    for (int k = 0; k < n; k++) {
        int u = u0 + k;
        int tile = u & 15, b = u >> 4;
        int ty0 = (tile >> 2) * 8, tx0 = (tile & 3) * 8;

        __syncthreads();
        for (int i = tid; i < 200; i += 256) {
            int ic = i / 100, r = (i / 10) % 10, c = i % 10;
            int gy = ty0 + r - 1, gx = tx0 + c - 1;
            float v = 0.f;
            if ((unsigned)gy < 32u && (unsigned)gx < 32u)
                v = bt[((b*2 + ic)*32 + gy)*32 + gx];
            xs[(ic*10 + r)*12 + c] = v;
        }
        __syncthreads();

        int p  = tid & 63;
        int cg = tid >> 6;
        int py = p >> 3, px = p & 7;
        int oc0 = cg * 16;

        float acc[16];
#pragma unroll
        for (int o = 0; o < 16; o++) acc[o] = 0.f;

#pragma unroll
        for (int ic = 0; ic < 2; ic++) {
            float xr[9];
#pragma unroll
            for (int r = 0; r < 3; r++)
#pragma unroll
                for (int c = 0; c < 3; c++)
                    xr[r*3 + c] = xs[(ic*10 + py + r)*12 + px + c];
#pragma unroll
            for (int kk = 0; kk < 9; kk++) {
                float x = xr[kk];
#pragma unroll
                for (int o = 0; o < 16; o++)
                    acc[o] = fmaf(x, ws[(oc0 + o)*19 + ic*9 + kk], acc[o]);
            }
        }

        int gy = ty0 + py, gx = tx0 + px;
#pragma unroll
        for (int o = 0; o < 16; o++) {
            int oc = oc0 + o;
            int idx = ((b*64 + oc)*32 + gy)*32 + gx;
            act0_out[idx] = liaf_pre(acc[o] + b0[oc], &g_c0_pre[idx]);
        }
    }
}

// ---------------- f32x2 conv (3x3) + LIAF + 2x2 pool + LIAF (v4 body) ----------
// NOG packed-oc pairs per thread; OCW = 32*NOG output channels per unit.
template<int HW, int TILE_R, int PXC, int CIN, int NOG>
__device__ __forceinline__ void conv_pool_unit(
    float* __restrict__ smem,
    const float* __restrict__ in, const float* __restrict__ Wt,
    const float* __restrict__ bias, float* __restrict__ conv_pre,
    float* __restrict__ pool_pre, float* __restrict__ pool_out,
    int ocbase, int t0r, int t0c, int b)
{
    constexpr int XROWS = TILE_R + 2;
    constexpr int XSTR  = 13;
    constexpr int PCOLS = 8 / PXC;
    constexpr int RW    = PXC + 2;
    constexpr int OCW   = 32 * NOG;
    float* xs = smem;                       // 8*XROWS*13 floats
    float* ws = smem + 8 * XROWS * XSTR;    // 72*OCW floats

    const int tid  = threadIdx.x;
    const int pos  = tid & 15;
    const int g    = tid >> 4;
    const int prow = pos / PCOLS;
    const int pcol = pos % PCOLS;
    const int qy   = prow * 2;
    const int qx   = pcol * PXC;

    ull acc[2][PXC][NOG];
#pragma unroll
    for (int py = 0; py < 2; py++)
#pragma unroll
        for (int px = 0; px < PXC; px++)
#pragma unroll
            for (int og = 0; og < NOG; og++) acc[py][px][og] = 0ull;

    for (int ch = 0; ch < CIN/8; ch++) {
        __syncthreads();
        for (int i = tid; i < 8 * XROWS * 10; i += 256) {
            int icl = i / (XROWS * 10);
            int rem = i - icl * (XROWS * 10);
            int r = rem / 10, c = rem - r * 10;
            int gy = t0r + r - 1, gx = t0c + c - 1;
            float v = 0.f;
            if ((unsigned)gy < (unsigned)HW && (unsigned)gx < (unsigned)HW)
                v = in[((b*CIN + ch*8 + icl)*HW + gy)*HW + gx];
            xs[(icl * XROWS + r) * XSTR + c] = v;
        }
        for (int i = tid; i < 72 * (OCW/4); i += 256) {
            int j = i / (OCW/4), q = i - j*(OCW/4);
            *(float4*)&ws[j*OCW + q*4] =
                *(const float4*)&Wt[(ch*72 + j)*128 + ocbase + q*4];
        }
        __syncthreads();

#pragma unroll 1
        for (int icl = 0; icl < 8; icl++) {
            const float* xb = &xs[icl * (XROWS * XSTR) + qx];
            const float* wb = &ws[icl * (9*OCW) + g*(2*NOG)];

            ull ra[RW], rb[RW];
#pragma unroll
            for (int c = 0; c < RW; c++) ra[c] = dup2(xb[(qy + 0) * XSTR + c]);
#pragma unroll
            for (int c = 0; c < RW; c++) rb[c] = dup2(xb[(qy + 1) * XSTR + c]);

#pragma unroll
            for (int ky = 0; ky < 3; ky++) {
                const ull* lo; const ull* hi;
                if (ky == 0) { lo = ra; hi = rb; }
                else if (ky == 1) { lo = rb; hi = ra; }
                else { lo = ra; hi = rb; }
#pragma unroll
                for (int kx = 0; kx < 3; kx++) {
                    ull wp[NOG];
#pragma unroll
                    for (int og = 0; og < NOG; og++)
                        wp[og] = *(const ull*)&wb[(ky*3 + kx)*OCW + og*2];
#pragma unroll
                    for (int px = 0; px < PXC; px++) {
#pragma unroll
                        for (int og = 0; og < NOG; og++) {
                            FMA2(acc[0][px][og], lo[px + kx], wp[og]);
                            FMA2(acc[1][px][og], hi[px + kx], wp[og]);
                        }
                    }
                }
                if (ky == 0) {
#pragma unroll
                    for (int c = 0; c < RW; c++) ra[c] = dup2(xb[(qy + 2) * XSTR + c]);
                } else if (ky == 1) {
#pragma unroll
                    for (int c = 0; c < RW; c++) rb[c] = dup2(xb[(qy + 3) * XSTR + c]);
                }
            }
        }
    }

    const int gy0 = t0r + qy, gx0 = t0c + qx;
#pragma unroll
    for (int og = 0; og < NOG; og++) {
#pragma unroll
        for (int half = 0; half < 2; half++) {
            int oc = ocbase + g*(2*NOG) + og*2 + half;
            float bv = bias[oc];
            float a[2][PXC];
#pragma unroll
            for (int py = 0; py < 2; py++)
#pragma unroll
                for (int px = 0; px < PXC; px++) {
                    F2 v; v.u = acc[py][px][og];
                    float u = (half ? v.f.y : v.f.x) + bv;
                    int idx = ((b*128 + oc)*HW + gy0 + py)*HW + gx0 + px;
                    a[py][px] = liaf_pre(u, &conv_pre[idx]);
                }
#pragma unroll
            for (int w = 0; w < PXC/2; w++) {
                float u = 0.25f * (((a[0][w*2] + a[0][w*2+1]) + a[1][w*2]) + a[1][w*2+1]);
                int pidx = ((b*128 + oc)*(HW/2) + (gy0 >> 1))*(HW/2) + (gx0 >> 1) + w;
                pool_out[pidx] = liaf_pre(u, &pool_pre[pidx]);
            }
        }
    }
}

// ---------------- fc2 block-unit (8 warps cover 8 of 396 (b,row) pairs) --------
__device__ __forceinline__ void fc2_unit(
    const float* __restrict__ Wf2, const float* __restrict__ bf2,
    const float* __restrict__ acth1_in, int unit)
{
    int warp = threadIdx.x >> 5, lane = threadIdx.x & 31;
    int gw = unit * 8 + warp;
    if (gw >= 396) return;
    int b = gw / 11, row = gw % 11;
    float s = 0.f;
#pragma unroll
    for (int k = lane; k < 256; k += 32)
        s += acth1_in[b*256 + k] * Wf2[row*256 + k];
#pragma unroll
    for (int off = 16; off; off >>= 1)
        s += __shfl_down_sync(0xffffffffu, s, off);
    if (lane == 0) {
        int idx = b*11 + row;
        float o = liaf_pre(s + bf2[row], &g_h2_pre[idx]);
        g_acc[idx] += o;
    }
}

// ---------------- fc1 block-unit (8 warps; gw = unit*8+warp) ----------------
__device__ __forceinline__ void fc1_unit(
    const float* __restrict__ Wf1, const float* __restrict__ bf1,
    const float* __restrict__ actp2_in, float* __restrict__ acth1_out, int unit)
{
    int warp = threadIdx.x >> 5, lane = threadIdx.x & 31;
    int gw = unit * 8 + warp;
    if (gw >= 1536) return;
    int o = gw / 6, bg = gw % 6;
    const float4* wp = (const float4*)(Wf1 + (size_t)o * 8192);
    float bv = bf1[o];
    int b0i = bg * 6;
    for (int b = b0i; b < b0i + 6; b++) {
        const float4* xp = (const float4*)(actp2_in + (size_t)b * 8192);
        float s = 0.f;
#pragma unroll 8
        for (int i = lane; i < 2048; i += 32) {
            float4 x = xp[i], w = wp[i];
            s += x.x*w.x; s += x.y*w.y; s += x.z*w.z; s += x.w*w.w;
        }
#pragma unroll
        for (int off = 16; off; off >>= 1)
            s += __shfl_down_sync(0xffffffffu, s, off);
        if (lane == 0) {
            int idx = b*256 + o;
            acth1_out[idx] = liaf_pre(s + bv, &g_h1_pre[idx]);
        }
    }
}

// ---------------- mega kernel: 5-stage pipeline, one barrier per phase ---------
// Heavy units: 1152 uniform (576 conv1 oc-halves + 576 conv2 oc-quarters).
// Per-SM (blk%148): SMs 0..115 -> 8 units, SMs 116..147 -> 7 units + all
// small work (conv0 batches, fc1, fc2) — co-resident with FMA-bound conv.
__global__ __launch_bounds__(256, 2) void mega_kernel(
    const float* __restrict__ W0, const float* __restrict__ b0,
    const float* __restrict__ b1, const float* __restrict__ b2,
    const float* __restrict__ Wf1, const float* __restrict__ bf1,
    const float* __restrict__ Wf2, const float* __restrict__ bf2,
    float* __restrict__ out)
{
    __shared__ __align__(16) float smem[6480];
    unsigned epoch = 0u;
    const int blk = blockIdx.x;
    const int tid = threadIdx.x;
    const int s   = blk % 148;         // SM slot
    const int m   = blk / 148;         // member within SM pair
    const int nsm = (s < 116) ? 8 : 7;
    const int base = (s < 116) ? s * 8 : 928 + (s - 116) * 7;
    const int ust = base + (m ? 4 : 0);
    const int uen = m ? (base + nsm) : (base + 4);

    for (int p = 0; p < TWIN + 4; p++) {
        int t1 = p - 1;   // conv1 step
        int t2 = p - 2;   // conv2 step
        int t3 = p - 3;   // fc1 step
        int t4 = p - 4;   // fc2 step

        // ---- conv1(t1): units [ust, min(uen,576)) ----
        if (t1 >= 0 && t1 < TWIN) {
            const float* a0 = g_act0[t1 & 1];
            float* ap1 = g_actp1[t1 & 1];
            int e1 = (uen < 576) ? uen : 576;
            for (int u = ust; u < e1; u++) {
                int bx = u & 15, b = u >> 4;
                int half = bx & 1, tc = (bx >> 1) & 3, tr = bx >> 3;
                conv_pool_unit<32, 16, 4, 64, 2>(smem, a0, g_Wt1, b1,
                    g_c1_pre, g_p1_pre, ap1, half * 64, tr * 16, tc * 8, b);
            }
        }

        // ---- conv2(t2) quarters: units [max(ust,576), uen) ----
        if (t2 >= 0 && t2 < TWIN) {
            const float* ap1 = g_actp1[t2 & 1];
            float* ap2 = g_actp2[t2 & 1];
            int s2 = (ust > 576) ? ust : 576;
            for (int u = s2; u < uen; u++) {
                int cu = u - 576;
                int b = cu >> 4, r = cu & 15;
                int q = r & 3, tile = r >> 2;
                int tr = tile >> 1, tc = tile & 1;
                conv_pool_unit<16, 8, 2, 128, 1>(smem, ap1, g_Wt2, b2,
                    g_c2_pre, g_p2_pre, ap2, q * 32, tr * 8, tc * 8, b);
            }
        }

        // ---- conv0(p): 576 units on light SMs, 18/SM (9 per block) ----
        if (p < TWIN && s >= 116)
            conv0_batch(smem, W0, b0, g_act0[p & 1], p,
                        (s - 116) * 18 + m * 9, 9);

        // ---- fc1(t3): 192 units on light SMs, 6/SM (3 per block) ----
        if (t3 >= 0 && t3 < TWIN && s >= 116) {
            const float* ap2 = g_actp2[t3 & 1];
            float* ah1 = g_acth1[t3 & 1];
            int f0 = (s - 116) * 6 + m * 3;
            for (int k = 0; k < 3; k++)
                fc1_unit(Wf1, bf1, ap2, ah1, f0 + k);
        }

        // ---- fc2(t4): 50 units on light-SM member-1 blocks (32 blocks) ----
        if (t4 >= 0 && t4 < TWIN && s >= 116 && m == 1) {
            const float* ah1 = g_acth1[t4 & 1];
            for (int u = s - 116; u < 50; u += 32)
                fc2_unit(Wf2, bf2, ah1, u);
        }

        grid_barrier(epoch);
    }

    if (blk == 0)
        for (int i = tid; i < BATCH*11; i += 256)
            out[i] = g_acc[i] * (1.0f / (float)TWIN);
}

extern "C" void kernel_launch(void* const* d_in, const int* in_sizes, int n_in,
                              void* d_out, int out_size) {
    (void)in_sizes; (void)n_in; (void)out_size;
    const float* data = (const float*)d_in[0];
    const float* W0  = (const float*)d_in[2];
    const float* b0  = (const float*)d_in[3];
    const float* W1  = (const float*)d_in[4];
    const float* b1  = (const float*)d_in[5];
    const float* W2  = (const float*)d_in[6];
    const float* b2  = (const float*)d_in[7];
    const float* Wf1 = (const float*)d_in[8];
    const float* bf1 = (const float*)d_in[9];
    const float* Wf2 = (const float*)d_in[10];
    const float* bf2 = (const float*)d_in[11];

    zero_state_kernel<<<(BATCH*128*32*32 + 255)/256, 256>>>();
    prep_weights_kernel<<<(1152*128 + 255)/256, 256>>>(W1, W2);
    prep_bin_kernel<<<(TWIN*BATCH*2*32*32 + 255)/256, 256>>>(data);
    mega_kernel<<<NBLOCKS, 256>>>(W0, b0, b1, b2, Wf1, bf1, Wf2, bf2,
                                  (float*)d_out);
}

// round 16
// speedup vs baseline: 1.5056x; 1.5056x over previous
#include <cuda_runtime.h>

typedef unsigned long long ull;

#define BATCH 36
#define TWIN 60
#define DECAY 0.3f
#define THRESH 0.5f
#define NBLOCKS 296

// packed f32x2 fma: d = a*b + d per 32-bit lane (bit-exact IEEE fma per lane)
#define FMA2(d, a, b) asm("fma.rn.f32x2 %0, %1, %2, %0;" : "+l"(d) : "l"(a), "l"(b))

#define CP_ASYNC4(dst, src)  asm volatile("cp.async.ca.shared.global [%0], [%1], 4;"  :: "r"(dst), "l"(src))
#define CP_ASYNC16(dst, src) asm volatile("cp.async.cg.shared.global [%0], [%1], 16;" :: "r"(dst), "l"(src))
#define CP_COMMIT()          asm volatile("cp.async.commit_group;" ::: "memory")
#define CP_WAIT0()           asm volatile("cp.async.wait_group 0;" ::: "memory")

union F2 { ull u; float2 f; };

__device__ __forceinline__ ull dup2(float v) {
    F2 d; d.f.x = v; d.f.y = v; return d.u;
}

__device__ __forceinline__ unsigned smem_u32(const void* p) {
    return (unsigned)__cvta_generic_to_shared(p);
}

// ---------------- persistent LIAF state: pre = (m>THRESH) ? 0 : m*DECAY ----------
__device__ __align__(16) float g_c0_pre[BATCH*64*32*32];
__device__ __align__(16) float g_c1_pre[BATCH*128*32*32];
__device__ __align__(16) float g_p1_pre[BATCH*128*16*16];
__device__ __align__(16) float g_c2_pre[BATCH*128*16*16];
__device__ __align__(16) float g_p2_pre[BATCH*128*8*8];
__device__ __align__(16) float g_h1_pre[BATCH*256];
__device__ __align__(16) float g_h2_pre[BATCH*11];
__device__ __align__(16) float g_acc[BATCH*11];

// ---------------- parity double-buffered activations ----------------
__device__ __align__(16) float g_act0 [2][BATCH*64*32*32];
__device__ __align__(16) float g_actp1[2][BATCH*128*16*16];
__device__ __align__(16) float g_actp2[2][BATCH*128*8*8];
__device__ __align__(16) float g_acth1[2][BATCH*256];

// ---------------- pre-binarized input, t-major: [t][b*2+ic][y][x] ----------------
__device__ __align__(16) float g_bin[TWIN*BATCH*2*32*32];

// ---------------- transposed weights: Wt[c][oc], c = ic*9 + k ----------------
__device__ __align__(16) float g_Wt1[576*128];   // conv1: 64*9 x 128
__device__ __align__(16) float g_Wt2[1152*128];  // conv2: 128*9 x 128

// ---------------- global barrier state ----------------
__device__ unsigned g_bar_count;
__device__ unsigned g_bar_epoch;

__device__ __forceinline__ float liaf_pre(float u, float* prep) {
    float m = *prep + u;
    *prep = (m > THRESH) ? 0.0f : m * DECAY;
    return fmaxf(m, 0.0f);
}

// ---------------- zero state (+ barrier reset) ----------------
__global__ void zero_state_kernel() {
    int i = blockIdx.x * blockDim.x + threadIdx.x;
    if (i == 0) { g_bar_count = 0u; g_bar_epoch = 0u; }
    if (i < BATCH*64*32*32)  g_c0_pre[i] = 0.f;
    if (i < BATCH*128*32*32) g_c1_pre[i] = 0.f;
    if (i < BATCH*128*16*16) { g_p1_pre[i] = 0.f; g_c2_pre[i] = 0.f; }
    if (i < BATCH*128*8*8)   g_p2_pre[i] = 0.f;
    if (i < BATCH*256)       g_h1_pre[i] = 0.f;
    if (i < BATCH*11)        { g_h2_pre[i] = 0.f; g_acc[i] = 0.f; }
}

// ---------------- weight transpose (once per launch) ----------------
__global__ void prep_weights_kernel(const float* __restrict__ W1,
                                    const float* __restrict__ W2) {
    int i = blockIdx.x * blockDim.x + threadIdx.x;
    if (i < 576*128)  g_Wt1[i] = W1[(i & 127)*576  + (i >> 7)];
    if (i < 1152*128) g_Wt2[i] = W2[(i & 127)*1152 + (i >> 7)];
}

// ---------------- input binarize + transpose (once per launch) ----------------
__global__ void prep_bin_kernel(const float* __restrict__ data) {
    int i = blockIdx.x * blockDim.x + threadIdx.x;
    if (i >= TWIN*BATCH*2*32*32) return;
    int t = i / 73728, sp = i - t * 73728;
    g_bin[i] = (data[(size_t)sp * TWIN + t] > 1.0f) ? 1.0f : 0.0f;
}

// ---------------- device grid barrier (all NBLOCKS blocks) ----------------
__device__ __forceinline__ void grid_barrier(unsigned& epoch) {
    __syncthreads();
    if (threadIdx.x == 0) {
        __threadfence();                       // publish this block's writes
        unsigned arrived = atomicAdd(&g_bar_count, 1u);
        if (arrived == NBLOCKS - 1u) {
            g_bar_count = 0u;
            __threadfence();
            atomicAdd(&g_bar_epoch, 1u);       // release
        } else {
            unsigned target = epoch + 1u, e;
            do {
                asm volatile("ld.acquire.gpu.u32 %0, [%1];"
                             : "=r"(e) : "l"(&g_bar_epoch) : "memory");
                if (e < target) __nanosleep(64);
            } while (e < target);
        }
    }
    __syncthreads();
    epoch += 1u;
    __threadfence();   // gpu-scope fence: drop stale L1 lines before next phase
}

// ---------------- conv0 unit: prebinarized 2->64 conv + LIAF ----------------
__device__ __forceinline__ void conv0_unit(
    float* __restrict__ smem,
    const float* __restrict__ W0, const float* __restrict__ b0,
    float* __restrict__ act0_out, int t, int tile, int b)
{
    float* xs = smem;            // [2][10][12] = 240
    float* ws = smem + 240;      // [64][19]    = 1216
    int ty0 = (tile >> 2) * 8, tx0 = (tile & 3) * 8;
    int tid = threadIdx.x;
    const float* bt = g_bin + (size_t)t * 73728;

    __syncthreads();
    for (int i = tid; i < 200; i += 256) {
        int ic = i / 100, r = (i / 10) % 10, c = i % 10;
        int gy = ty0 + r - 1, gx = tx0 + c - 1;
        float v = 0.f;
        if ((unsigned)gy < 32u && (unsigned)gx < 32u)
            v = bt[((b*2 + ic)*32 + gy)*32 + gx];
        xs[(ic*10 + r)*12 + c] = v;
    }
    for (int i = tid; i < 1152; i += 256) {
        int oc = i / 18, r = i % 18;
        ws[oc*19 + r] = W0[i];
    }
    __syncthreads();

    int p  = tid & 63;
    int cg = tid >> 6;
    int py = p >> 3, px = p & 7;
    int oc0 = cg * 16;

    float acc[16];
#pragma unroll
    for (int o = 0; o < 16; o++) acc[o] = 0.f;

#pragma unroll
    for (int ic = 0; ic < 2; ic++) {
        float xr[9];
#pragma unroll
        for (int r = 0; r < 3; r++)
#pragma unroll
            for (int c = 0; c < 3; c++)
                xr[r*3 + c] = xs[(ic*10 + py + r)*12 + px + c];
#pragma unroll
        for (int k = 0; k < 9; k++) {
            float x = xr[k];
#pragma unroll
            for (int o = 0; o < 16; o++)
                acc[o] = fmaf(x, ws[(oc0 + o)*19 + ic*9 + k], acc[o]);
        }
    }

    int gy = ty0 + py, gx = tx0 + px;
#pragma unroll
    for (int o = 0; o < 16; o++) {
        int oc = oc0 + o;
        int idx = ((b*64 + oc)*32 + gy)*32 + gx;
        act0_out[idx] = liaf_pre(acc[o] + b0[oc], &g_c0_pre[idx]);
    }
}

// ---------------- f32x2 conv (3x3) + LIAF + 2x2 pool + LIAF -------------------
// v5: cp.async double-buffered chunk staging. One chunk = 4 input channels:
// x[4][XROWS][13] + w[36][64]. Two chunk buffers fit in the 6480-float smem.
// Compute body identical to v4; accumulation order unchanged (chunks ascend
// exactly like the old (ch, icl) order).
template<int HW, int TILE_R, int PXC, int CIN>
__device__ __forceinline__ void conv_pool_unit(
    float* __restrict__ smem,
    const float* __restrict__ in, const float* __restrict__ Wt,
    const float* __restrict__ bias, float* __restrict__ conv_pre,
    float* __restrict__ pool_pre, float* __restrict__ pool_out,
    int ocbase, int t0r, int t0c, int b)
{
    constexpr int XROWS = TILE_R + 2;
    constexpr int XSTR  = 13;
    constexpr int PCOLS = 8 / PXC;
    constexpr int RW    = PXC + 2;
    constexpr int XCH   = 4 * XROWS * XSTR;     // x floats per chunk
    constexpr int WCH   = 36 * 64;              // w floats per chunk
    constexpr int BUF   = XCH + WCH;
    constexpr int NCHUNK = CIN / 4;

    const int tid  = threadIdx.x;
    const int pos  = tid & 15;
    const int g    = tid >> 4;
    const int prow = pos / PCOLS;
    const int pcol = pos % PCOLS;
    const int qy   = prow * 2;
    const int qx   = pcol * PXC;

    // pre-zero x regions of both buffers (halo positions stay 0 forever)
    __syncthreads();
    for (int i = tid; i < XCH; i += 256) { smem[i] = 0.f; smem[BUF + i] = 0.f; }
    __syncthreads();

    // chunk staging via cp.async
    auto stage = [&](int c, float* dst) {
        int ch = c >> 1, hf = c & 1;
        unsigned dx = smem_u32(dst);
        // x: 4 channels, in-range positions only
        for (int i = tid; i < 4 * XROWS * 10; i += 256) {
            int il = i / (XROWS * 10);
            int rem = i - il * (XROWS * 10);
            int r = rem / 10, cc = rem - r * 10;
            int gy = t0r + r - 1, gx = t0c + cc - 1;
            if ((unsigned)gy < (unsigned)HW && (unsigned)gx < (unsigned)HW) {
                const float* src =
                    &in[((b*CIN + ch*8 + hf*4 + il)*HW + gy)*HW + gx];
                CP_ASYNC4(dx + ((il*XROWS + r)*XSTR + cc)*4, src);
            }
        }
        // w: 36 rows x 64 oc, float4 granularity
        unsigned dw = dx + XCH*4;
        for (int i = tid; i < 36 * 16; i += 256) {
            int j = i >> 4, q = i & 15;
            const float* src = &Wt[(ch*72 + hf*36 + j)*128 + ocbase + q*4];
            CP_ASYNC16(dw + (j*64 + q*4)*4, src);
        }
        CP_COMMIT();
    };

    ull acc[2][PXC][2];
#pragma unroll
    for (int py = 0; py < 2; py++)
#pragma unroll
        for (int px = 0; px < PXC; px++) {
            acc[py][px][0] = 0ull; acc[py][px][1] = 0ull;
        }

    stage(0, smem);

    for (int c = 0; c < NCHUNK; c++) {
        CP_WAIT0();
        __syncthreads();
        if (c + 1 < NCHUNK) stage(c + 1, ((c + 1) & 1) ? smem + BUF : smem);
        const float* cur = (c & 1) ? smem + BUF : smem;
        const float* xsb = cur;
        const float* wsb = cur + XCH;

#pragma unroll 1
        for (int il = 0; il < 4; il++) {
            const float* xb = &xsb[il * (XROWS * XSTR) + qx];
            const float* wb = &wsb[il * (9*64) + g*4];

            ull ra[RW], rb[RW];
#pragma unroll
            for (int cc = 0; cc < RW; cc++) ra[cc] = dup2(xb[(qy + 0) * XSTR + cc]);
#pragma unroll
            for (int cc = 0; cc < RW; cc++) rb[cc] = dup2(xb[(qy + 1) * XSTR + cc]);

#pragma unroll
            for (int ky = 0; ky < 3; ky++) {
                const ull* lo; const ull* hi;
                if (ky == 0) { lo = ra; hi = rb; }
                else if (ky == 1) { lo = rb; hi = ra; }
                else { lo = ra; hi = rb; }
#pragma unroll
                for (int kx = 0; kx < 3; kx++) {
                    ull w0 = *(const ull*)&wb[(ky*3 + kx)*64];
                    ull w1 = *(const ull*)&wb[(ky*3 + kx)*64 + 2];
#pragma unroll
                    for (int px = 0; px < PXC; px++) {
                        FMA2(acc[0][px][0], lo[px + kx], w0);
                        FMA2(acc[0][px][1], lo[px + kx], w1);
                        FMA2(acc[1][px][0], hi[px + kx], w0);
                        FMA2(acc[1][px][1], hi[px + kx], w1);
                    }
                }
                if (ky == 0) {
#pragma unroll
                    for (int cc = 0; cc < RW; cc++) ra[cc] = dup2(xb[(qy + 2) * XSTR + cc]);
                } else if (ky == 1) {
#pragma unroll
                    for (int cc = 0; cc < RW; cc++) rb[cc] = dup2(xb[(qy + 3) * XSTR + cc]);
                }
            }
        }
        __syncthreads();   // compute done before buffer may be re-staged next iter
    }

    const int gy0 = t0r + qy, gx0 = t0c + qx;
#pragma unroll
    for (int og = 0; og < 2; og++) {
#pragma unroll
        for (int half = 0; half < 2; half++) {
            int oc = ocbase + g*4 + og*2 + half;
            float bv = bias[oc];
            float a[2][PXC];
#pragma unroll
            for (int py = 0; py < 2; py++)
#pragma unroll
                for (int px = 0; px < PXC; px++) {
                    F2 v; v.u = acc[py][px][og];
                    float u = (half ? v.f.y : v.f.x) + bv;
                    int idx = ((b*128 + oc)*HW + gy0 + py)*HW + gx0 + px;
                    a[py][px] = liaf_pre(u, &conv_pre[idx]);
                }
#pragma unroll
            for (int w = 0; w < PXC/2; w++) {
                float u = 0.25f * (((a[0][w*2] + a[0][w*2+1]) + a[1][w*2]) + a[1][w*2+1]);
                int pidx = ((b*128 + oc)*(HW/2) + (gy0 >> 1))*(HW/2) + (gx0 >> 1) + w;
                pool_out[pidx] = liaf_pre(u, &pool_pre[pidx]);
            }
        }
    }
}

// ---------------- fc2 block-unit (8 warps cover 8 of 396 (b,row) pairs) --------
__device__ __forceinline__ void fc2_unit(
    const float* __restrict__ Wf2, const float* __restrict__ bf2,
    const float* __restrict__ acth1_in, int unit)
{
    int warp = threadIdx.x >> 5, lane = threadIdx.x & 31;
    int gw = unit * 8 + warp;
    if (gw >= 396) return;
    int b = gw / 11, row = gw % 11;
    float s = 0.f;
#pragma unroll
    for (int k = lane; k < 256; k += 32)
        s += acth1_in[b*256 + k] * Wf2[row*256 + k];
#pragma unroll
    for (int off = 16; off; off >>= 1)
        s += __shfl_down_sync(0xffffffffu, s, off);
    if (lane == 0) {
        int idx = b*11 + row;
        float o = liaf_pre(s + bf2[row], &g_h2_pre[idx]);
        g_acc[idx] += o;
    }
}

// ---------------- fc1 block-unit (8 warps; gw = unit*8+warp) ----------------
__device__ __forceinline__ void fc1_unit(
    const float* __restrict__ Wf1, const float* __restrict__ bf1,
    const float* __restrict__ actp2_in, float* __restrict__ acth1_out, int unit)
{
    int warp = threadIdx.x >> 5, lane = threadIdx.x & 31;
    int gw = unit * 8 + warp;
    if (gw >= 1536) return;
    int o = gw / 6, bg = gw % 6;
    const float4* wp = (const float4*)(Wf1 + (size_t)o * 8192);
    float bv = bf1[o];
    int b0i = bg * 6;
    for (int b = b0i; b < b0i + 6; b++) {
        const float4* xp = (const float4*)(actp2_in + (size_t)b * 8192);
        float s = 0.f;
#pragma unroll 8
        for (int i = lane; i < 2048; i += 32) {
            float4 x = xp[i], w = wp[i];
            s += x.x*w.x; s += x.y*w.y; s += x.z*w.z; s += x.w*w.w;
        }
#pragma unroll
        for (int off = 16; off; off >>= 1)
            s += __shfl_down_sync(0xffffffffu, s, off);
        if (lane == 0) {
            int idx = b*256 + o;
            acth1_out[idx] = liaf_pre(s + bv, &g_h1_pre[idx]);
        }
    }
}

// ---------------- mega kernel: 5-stage pipeline, ONE barrier per phase ---------
// phase p: conv1(p-1) | conv2(p-2) | conv0(p) | fc1(p-3) | fc2(p-4)
// (exact R12 schedule — best known)
__global__ __launch_bounds__(256, 2) void mega_kernel(
    const float* __restrict__ W0, const float* __restrict__ b0,
    const float* __restrict__ b1, const float* __restrict__ b2,
    const float* __restrict__ Wf1, const float* __restrict__ bf1,
    const float* __restrict__ Wf2, const float* __restrict__ bf2,
    float* __restrict__ out)
{
    __shared__ __align__(16) float smem[6480];
    unsigned epoch = 0u;
    const int blk = blockIdx.x;
    const int tid = threadIdx.x;

    for (int p = 0; p < TWIN + 4; p++) {
        int t1 = p - 1;   // conv1 step
        int t2 = p - 2;   // conv2 step
        int t3 = p - 3;   // fc1 step
        int t4 = p - 4;   // fc2 step

        // ---- conv1(t1): 576 units, strided ----
        if (t1 >= 0 && t1 < TWIN) {
            const float* a0 = g_act0[t1 & 1];
            float* ap1 = g_actp1[t1 & 1];
            for (int u = blk; u < 576; u += NBLOCKS) {
                int bx = u & 15, b = u >> 4;
                int half = bx & 1, tc = (bx >> 1) & 3, tr = bx >> 3;
                conv_pool_unit<32, 16, 4, 64>(smem, a0, g_Wt1, b1,
                    g_c1_pre, g_p1_pre, ap1, half * 64, tr * 16, tc * 8, b);
            }
        }

        // ---- conv2(t2): 288 units on blocks 0..287 ----
        if (t2 >= 0 && t2 < TWIN && blk < 288) {
            const float* ap1 = g_actp1[t2 & 1];
            float* ap2 = g_actp2[t2 & 1];
            int u = blk;
            int bx = u & 7, b = u >> 3;
            int half = bx & 1, tc = (bx >> 1) & 1, tr = bx >> 2;
            conv_pool_unit<16, 8, 2, 128>(smem, ap1, g_Wt2, b2,
                g_c2_pre, g_p2_pre, ap2, half * 64, tr * 8, tc * 8, b);
        }

        // ---- conv0(p): 576 units, weighted assignment ----
        if (p < TWIN) {
            float* a0 = g_act0[p & 1];
            if (blk < 280) {
                for (int u = blk; u < 432; u += 280)
                    conv0_unit(smem, W0, b0, a0, p, u & 15, u >> 4);
            } else {
                int u0 = 432 + (blk - 280) * 9;
                for (int u = u0; u < u0 + 9; u++)
                    conv0_unit(smem, W0, b0, a0, p, u & 15, u >> 4);
            }
        }

        // ---- fc1(t3): 192 units, one per block on 104..295 ----
        if (t3 >= 0 && t3 < TWIN && blk >= 104)
            fc1_unit(Wf1, bf1, g_actp2[t3 & 1], g_acth1[t3 & 1], blk - 104);

        // ---- fc2(t4): 50 units on blocks 288..295 ----
        if (t4 >= 0 && t4 < TWIN && blk >= 288) {
            const float* ah1 = g_acth1[t4 & 1];
            for (int u = blk - 288; u < 50; u += 8)
                fc2_unit(Wf2, bf2, ah1, u);
        }

        grid_barrier(epoch);
    }

    if (blk == 0)
        for (int i = tid; i < BATCH*11; i += 256)
            out[i] = g_acc[i] * (1.0f / (float)TWIN);
}

extern "C" void kernel_launch(void* const* d_in, const int* in_sizes, int n_in,
                              void* d_out, int out_size) {
    (void)in_sizes; (void)n_in; (void)out_size;
    const float* data = (const float*)d_in[0];
    const float* W0  = (const float*)d_in[2];
    const float* b0  = (const float*)d_in[3];
    const float* W1  = (const float*)d_in[4];
    const float* b1  = (const float*)d_in[5];
    const float* W2  = (const float*)d_in[6];
    const float* b2  = (const float*)d_in[7];
    const float* Wf1 = (const float*)d_in[8];
    const float* bf1 = (const float*)d_in[9];
    const float* Wf2 = (const float*)d_in[10];
    const float* bf2 = (const float*)d_in[11];

    zero_state_kernel<<<(BATCH*128*32*32 + 255)/256, 256>>>();
    prep_weights_kernel<<<(1152*128 + 255)/256, 256>>>(W1, W2);
    prep_bin_kernel<<<(TWIN*BATCH*2*32*32 + 255)/256, 256>>>(data);
    mega_kernel<<<NBLOCKS, 256>>>(W0, b0, b1, b2, Wf1, bf1, Wf2, bf2,
                                  (float*)d_out);
}